// round 15
// baseline (speedup 1.0000x reference)
#include <cuda_runtime.h>
#include <cuda_fp16.h>
#include <math.h>
#include <stdint.h>

// Problem constants
#define BQ   16
#define NQ   8192
#define SQ   2048
#define C1Q  128
#define C2Q  256
#define PQ   (BQ * NQ)      // 131072 points
#define KX   384            // C1 + C2 (GEMM1 K)
#define M0Q  256            // layer0 out channels
#define M1Q  128            // layer1 out channels
#define BN_EPS 1e-5f

// ---------------- scratch (static device globals; no cudaMalloc) ------------
__device__ float g_b0f[M0Q];
__device__ float g_b1f[M1Q];
__device__ __half g_w0h[M0Q * KX];                      // fp16 folded W0
__device__ __half g_w1h[M1Q * M0Q];                     // fp16 folded W1
__device__ float g_f2t[BQ * SQ * C2Q];                  // features_2 transposed [b][s][c]
__device__ __half g_xh[(size_t)PQ * KX];                // X hi fp16, K-major [p][k]
__device__ __half g_xl[(size_t)PQ * KX];                // X lo fp16
__device__ int   g_idx[PQ * 3];
__device__ float g_wt[PQ * 3];

// ---------------- PTX helpers (sm_80-level only; NO tcgen05) ----------------
__device__ __forceinline__ uint32_t smem_u32(const void* p) {
    uint32_t r;
    asm("{ .reg .u64 t; cvta.to.shared.u64 t, %1; cvt.u32.u64 %0, t; }" : "=r"(r) : "l"(p));
    return r;
}
__device__ __forceinline__ void cp16(uint32_t dst, const void* src) {
    asm volatile("cp.async.cg.shared.global [%0], [%1], 16;" :: "r"(dst), "l"(src));
}
#define CP_COMMIT() asm volatile("cp.async.commit_group;" ::: "memory")
#define CP_WAIT0()  asm volatile("cp.async.wait_group 0;" ::: "memory")
#define CP_WAIT1()  asm volatile("cp.async.wait_group 1;" ::: "memory")

#define SWZ(o) ((uint32_t)(o) ^ ((((uint32_t)(o)) >> 3) & 0x70u))

__device__ __forceinline__ void ldsm4(uint32_t& r0, uint32_t& r1, uint32_t& r2,
                                      uint32_t& r3, uint32_t addr) {
    asm volatile("ldmatrix.sync.aligned.m8n8.x4.shared.b16 {%0,%1,%2,%3}, [%4];"
                 : "=r"(r0), "=r"(r1), "=r"(r2), "=r"(r3) : "r"(addr));
}
// fp16 MMA with fp32 accumulate
__device__ __forceinline__ void mma16816(float* d, uint32_t a0, uint32_t a1,
                                         uint32_t a2, uint32_t a3,
                                         uint32_t b0, uint32_t b1) {
    asm volatile(
        "mma.sync.aligned.m16n8k16.row.col.f32.f16.f16.f32 "
        "{%0,%1,%2,%3}, {%4,%5,%6,%7}, {%8,%9}, {%0,%1,%2,%3};"
        : "+f"(d[0]), "+f"(d[1]), "+f"(d[2]), "+f"(d[3])
        : "r"(a0), "r"(a1), "r"(a2), "r"(a3), "r"(b0), "r"(b1));
}

// fp16 hi/lo split of two floats, packed into two uint32 (lo16=v0, hi16=v1)
__device__ __forceinline__ void split_pack(float v0, float v1, uint32_t& ph, uint32_t& plo) {
    __half h0 = __float2half_rn(v0), h1 = __float2half_rn(v1);
    float r0 = v0 - __half2float(h0), r1 = v1 - __half2float(h1);
    __half l0 = __float2half_rn(r0), l1 = __float2half_rn(r1);
    ph  = (uint32_t)__half_as_ushort(h0) | ((uint32_t)__half_as_ushort(h1) << 16);
    plo = (uint32_t)__half_as_ushort(l0) | ((uint32_t)__half_as_ushort(l1) << 16);
}

// ---------------- transpose features_2 + BN folds (merged) -------------------
__global__ void transpose_fold_kernel(const float* __restrict__ f2,
                                      const float* __restrict__ w0, const float* __restrict__ b0,
                                      const float* __restrict__ g0, const float* __restrict__ be0,
                                      const float* __restrict__ m0, const float* __restrict__ v0,
                                      const float* __restrict__ w1, const float* __restrict__ b1,
                                      const float* __restrict__ g1, const float* __restrict__ be1,
                                      const float* __restrict__ m1, const float* __restrict__ v1) {
    if (blockIdx.x == 64) {
        int tid  = threadIdx.y * 32 + threadIdx.x;                      // 0..255
        int base = (blockIdx.y * 16 + blockIdx.z) * 256 + tid;          // 0..32767
        for (int e = base; e < M0Q * KX; e += 32768) {
            int o = e / KX;
            float s = g0[o] * rsqrtf(v0[o] + BN_EPS);
            g_w0h[e] = __float2half_rn(w0[e] * s);
        }
        {
            int e = base;
            int o = e >> 8;
            float s = g1[o] * rsqrtf(v1[o] + BN_EPS);
            g_w1h[e] = __float2half_rn(w1[e] * s);
        }
        if (base < M0Q) {
            float s = g0[base] * rsqrtf(v0[base] + BN_EPS);
            g_b0f[base] = (b0[base] - m0[base]) * s + be0[base];
        }
        if (base < M1Q) {
            float s = g1[base] * rsqrtf(v1[base] + BN_EPS);
            g_b1f[base] = (b1[base] - m1[base]) * s + be1[base];
        }
        return;
    }
    __shared__ float tile[32][33];
    int b  = blockIdx.z;
    int s0 = blockIdx.x * 32;
    int c0 = blockIdx.y * 32;
    int tx = threadIdx.x, ty = threadIdx.y;
    int s = s0 + tx;
#pragma unroll
    for (int r = 0; r < 4; r++) {
        int c = c0 + ty + r * 8;
        tile[ty + r * 8][tx] = f2[((size_t)b * C2Q + c) * SQ + s];
    }
    __syncthreads();
    int c = c0 + tx;
#pragma unroll
    for (int r = 0; r < 4; r++) {
        int s2 = s0 + ty + r * 8;
        g_f2t[((size_t)b * SQ + s2) * C2Q + c] = tile[tx][ty + r * 8];
    }
}

// ---------------- 3-NN, two-phase: fast FMA top-4 scan + exact reselect ------
// Pass 1 uses FMA-contracted distances (cheap) to find the top-4 candidates.
// Pass 2 recomputes the reference-rounded distance for those 4 only and
// selects the top-3 with stable (d, order) ranking. The exact top-3 is in the
// fast top-4 unless four candidates lie within ~2e-7 of each other (never in
// practice). Weights use the exact distances.
__global__ __launch_bounds__(256) void knn_kernel(const float* __restrict__ c1,
                                                  const float* __restrict__ c2) {
    __shared__ float4 sc[SQ];
    int b = blockIdx.y;
    const float* cb = c2 + (size_t)b * 3 * SQ;
    for (int i = threadIdx.x; i < SQ; i += 256) {
        float x = cb[i], y = cb[SQ + i], z = cb[2 * SQ + i];
        // sq uses reference rounding (also consumed by the exact recompute)
        float sq = __fadd_rn(__fadd_rn(__fmul_rn(x, x), __fmul_rn(y, y)), __fmul_rn(z, z));
        sc[i] = make_float4(x, y, z, sq);
    }
    __syncthreads();

    int n = blockIdx.x * 256 + threadIdx.x;
    const float* qb = c1 + (size_t)b * 3 * NQ;
    float x1 = qb[n], y1 = qb[NQ + n], z1 = qb[2 * NQ + n];
    float q2 = __fadd_rn(__fadd_rn(__fmul_rn(x1, x1), __fmul_rn(y1, y1)), __fmul_rn(z1, z1));

    // ---- pass 1: fast top-4 ----
    float d0 = 1e30f, d1 = 1e30f, d2 = 1e30f, d3 = 1e30f;
    int   i0 = 0, i1 = 0, i2 = 0, i3 = 0;
#pragma unroll 4
    for (int s = 0; s < SQ; s++) {
        float4 c = sc[s];
        float dot = fmaf(x1, c.x, fmaf(y1, c.y, z1 * c.z));
        float d = fmaf(-2.0f, dot, q2 + c.w);
        if (d < d3) {
            if (d < d1) {
                if (d < d0) {
                    d3 = d2; i3 = i2; d2 = d1; i2 = i1; d1 = d0; i1 = i0; d0 = d; i0 = s;
                } else {
                    d3 = d2; i3 = i2; d2 = d1; i2 = i1; d1 = d; i1 = s;
                }
            } else {
                if (d < d2) { d3 = d2; i3 = i2; d2 = d; i2 = s; }
                else        { d3 = d;  i3 = s; }
            }
        }
    }

    // ---- pass 2: exact distances for the 4 survivors ----
    float ed[4];
    int   ei[4] = {i0, i1, i2, i3};
#pragma unroll
    for (int j = 0; j < 4; j++) {
        float4 c = sc[ei[j]];
        float dot = __fadd_rn(__fadd_rn(__fmul_rn(x1, c.x), __fmul_rn(y1, c.y)),
                              __fmul_rn(z1, c.z));
        ed[j] = __fsub_rn(__fadd_rn(q2, c.w), __fadd_rn(dot, dot));
    }
    // stable 4-element sort by (d, index) ascending — sorting network
#pragma unroll
    for (int pass = 0; pass < 2; pass++) {
        // pairs (0,1),(2,3) then (0,2),(1,3) then (1,2) — unrolled below
    }
    {
        auto cswap = [&](int a, int bj) {
            bool sw = (ed[bj] < ed[a]) || (ed[bj] == ed[a] && ei[bj] < ei[a]);
            if (sw) {
                float td = ed[a]; ed[a] = ed[bj]; ed[bj] = td;
                int   ti = ei[a]; ei[a] = ei[bj]; ei[bj] = ti;
            }
        };
        cswap(0, 1); cswap(2, 3); cswap(0, 2); cswap(1, 3); cswap(1, 2);
    }
    d0 = ed[0]; d1 = ed[1]; d2 = ed[2];
    i0 = ei[0]; i1 = ei[1]; i2 = ei[2];

    d0 = fmaxf(d0, 1e-10f); d1 = fmaxf(d1, 1e-10f); d2 = fmaxf(d2, 1e-10f);
    float r0 = __fdiv_rn(1.0f, d0), r1 = __fdiv_rn(1.0f, d1), r2 = __fdiv_rn(1.0f, d2);
    float rs = __fadd_rn(__fadd_rn(r0, r1), r2);
    int p = b * NQ + n;
    g_idx[p * 3 + 0] = i0; g_idx[p * 3 + 1] = i1; g_idx[p * 3 + 2] = i2;
    g_wt[p * 3 + 0] = __fdiv_rn(r0, rs);
    g_wt[p * 3 + 1] = __fdiv_rn(r1, rs);
    g_wt[p * 3 + 2] = __fdiv_rn(r2, rs);
}

// ---------------- buildX: gather/interpolate + f1 copy -> X fp16 hi/lo -------
__global__ __launch_bounds__(256) void buildx_kernel(const float* __restrict__ f1) {
    __shared__ float tile[32][257];
    __shared__ int   sidx[32][3];
    __shared__ float swt[32][3];
    int p0 = blockIdx.x * 32;
    int b  = p0 >> 13;
    int n0 = p0 & (NQ - 1);
    int t = threadIdx.x;
    if (t < 96) {
        int pl = t / 3, k = t - pl * 3;
        sidx[pl][k] = g_idx[(p0 + pl) * 3 + k];
        swt[pl][k]  = g_wt[(p0 + pl) * 3 + k];
    }
    __syncthreads();

    uint32_t* xh = (uint32_t*)g_xh;
    uint32_t* xl = (uint32_t*)g_xl;
    int warp = t >> 5, lane = t & 31;

    // ---- phase A: gather + interpolate ----
    const float* fbase = g_f2t + (size_t)b * SQ * C2Q;
#pragma unroll
    for (int it = 0; it < 4; it++) {
        int pl = warp * 4 + it;
        const float* fa = fbase + (size_t)sidx[pl][0] * C2Q;
        const float* fb = fbase + (size_t)sidx[pl][1] * C2Q;
        const float* fc = fbase + (size_t)sidx[pl][2] * C2Q;
        float w0 = swt[pl][0], w1 = swt[pl][1], w2 = swt[pl][2];
#pragma unroll
        for (int q = 0; q < 2; q++) {
            int c = lane * 4 + q * 128;
            float4 a = *(const float4*)(fa + c);
            float4 bb = *(const float4*)(fb + c);
            float4 cv = *(const float4*)(fc + c);
            tile[pl][c + 0] = __fadd_rn(__fadd_rn(__fmul_rn(a.x, w0), __fmul_rn(bb.x, w1)), __fmul_rn(cv.x, w2));
            tile[pl][c + 1] = __fadd_rn(__fadd_rn(__fmul_rn(a.y, w0), __fmul_rn(bb.y, w1)), __fmul_rn(cv.y, w2));
            tile[pl][c + 2] = __fadd_rn(__fadd_rn(__fmul_rn(a.z, w0), __fmul_rn(bb.z, w1)), __fmul_rn(cv.z, w2));
            tile[pl][c + 3] = __fadd_rn(__fadd_rn(__fmul_rn(a.w, w0), __fmul_rn(bb.w, w1)), __fmul_rn(cv.w, w2));
        }
    }
    __syncthreads();
#pragma unroll
    for (int it = 0; it < 16; it++) {
        int i = t + it * 256;
        int pl = i >> 7, c2 = i & 127;
        uint32_t ph, plo;
        split_pack(tile[pl][c2 * 2], tile[pl][c2 * 2 + 1], ph, plo);
        size_t p = (size_t)(p0 + pl);
        xh[p * (KX / 2) + 64 + c2] = ph;
        xl[p * (KX / 2) + 64 + c2] = plo;
    }
    __syncthreads();

    // ---- phase B: features_1 copy through tile ----
#pragma unroll
    for (int it = 0; it < 16; it++) {
        int i = t + it * 256;            // 0..4095
        int c = i >> 5, n = i & 31;
        tile[n][c] = f1[((size_t)b * C1Q + c) * NQ + n0 + n];
    }
    __syncthreads();
#pragma unroll
    for (int it = 0; it < 8; it++) {
        int i = t + it * 256;            // 0..2047
        int pl = i >> 6, c2 = i & 63;
        uint32_t ph, plo;
        split_pack(tile[pl][c2 * 2], tile[pl][c2 * 2 + 1], ph, plo);
        size_t p = (size_t)(p0 + pl);
        xh[p * (KX / 2) + c2] = ph;
        xl[p * (KX / 2) + c2] = plo;
    }
}

// ---------------- fused GEMM1+GEMM2 (fp16x2 mma.sync) ------------------------
// Phase 1 (gemm1): CTA 128x256, warp tile 64x64, K=384 from gmem (double buf).
// Y (bias+relu, fp16 hi/lo split) is written to SMEM instead of gmem.
// Phase 2 (gemm2): same CTA contracts K=256 over the SMEM-resident Y with
// W1 (prefetched at kernel start), writes final output.
__global__ __launch_bounds__(256, 1) void gemm_fused_kernel(float* __restrict__ outF) {
    constexpr int NCH    = KX / 64;            // 6
    constexpr int ATILE  = 128 * 128;          // 16 KB per A half-chunk
    constexpr int BTILE  = M0Q * 128;          // 32 KB W0 chunk
    constexpr int CHUNK  = 2 * ATILE + BTILE;  // 64 KB
    constexpr int YBASE  = 0;
    constexpr int YLOFF  = 4 * 16384;          // 64 KB
    constexpr int WBASE  = 2 * CHUNK;          // 131072

    extern __shared__ __align__(1024) char dsm[];
    const uint32_t s0 = smem_u32(dsm);

    const int tid  = threadIdx.x;
    const int warp = tid >> 5;
    const int lane = tid & 31;
    const int wm   = warp >> 2;                // 0..1
    const int wn   = warp & 3;                 // 0..3
    const int p0   = blockIdx.x * 128;

    const int a_row = (lane & 15);
    const int a_k8  = (lane >> 4) * 8;
    const int b_row = ((lane >> 4) & 1) * 8 + (lane & 7);
    const int b_k8  = ((lane >> 3) & 1) * 8;

    // ---- prefetch W1 (64 KB) as the first cp.async group ----
    {
#pragma unroll
        for (int it = 0; it < 16; it++) {
            int i = tid + it * 256;            // 0..4095
            int kc  = i >> 10;                 // 0..3
            int r   = (i >> 3) & 127;
            int c16 = (i & 7) * 16;
            uint32_t dst = s0 + WBASE + kc * 16384 + SWZ(r * 128 + c16);
            const char* src = (const char*)g_w1h + (size_t)r * (M0Q * 2) + kc * 128 + c16;
            cp16(dst, src);
        }
        CP_COMMIT();
    }

    float acc[4][8][4];
#pragma unroll
    for (int mi = 0; mi < 4; mi++)
#pragma unroll
        for (int ni = 0; ni < 8; ni++)
#pragma unroll
            for (int e = 0; e < 4; e++) acc[mi][ni][e] = 0.0f;

    auto load_chunk = [&](int buf, int ch) {
        const uint32_t base = s0 + buf * CHUNK;
        const size_t rs = (size_t)KX * 2;
        const char* gAh = (const char*)g_xh + (size_t)p0 * rs + (size_t)ch * 128;
        const char* gAl = (const char*)g_xl + (size_t)p0 * rs + (size_t)ch * 128;
        const char* gWh = (const char*)g_w0h + (size_t)ch * 128;
#pragma unroll
        for (int it = 0; it < 4; it++) {
            int i = tid + it * 256;            // 0..1023 (A rows)
            int row = i >> 3, c16 = (i & 7) * 16;
            uint32_t sw = SWZ(row * 128 + c16);
            size_t go = (size_t)row * rs + c16;
            cp16(base + sw,         gAh + go);
            cp16(base + ATILE + sw, gAl + go);
        }
#pragma unroll
        for (int it = 0; it < 8; it++) {
            int i = tid + it * 256;            // 0..2047 (W rows)
            int row = i >> 3, c16 = (i & 7) * 16;
            uint32_t sw = SWZ(row * 128 + c16);
            size_t go = (size_t)row * rs + c16;
            cp16(base + 2 * ATILE + sw, gWh + go);
        }
        CP_COMMIT();
    };

    load_chunk(0, 0);
    load_chunk(1, 1);

    for (int c = 0; c < NCH; c++) {
        if (c + 1 < NCH) { CP_WAIT1(); } else { CP_WAIT0(); }
        __syncthreads();

        const uint32_t base = s0 + (c & 1) * CHUNK;
#pragma unroll
        for (int kk = 0; kk < 4; kk++) {
            const int kb = (kk * 16 + a_k8) * 2;
            uint32_t ah[4][4], al[4][4];
#pragma unroll
            for (int mi = 0; mi < 4; mi++) {
                uint32_t off = SWZ((wm * 64 + mi * 16 + a_row) * 128 + kb);
                ldsm4(ah[mi][0], ah[mi][1], ah[mi][2], ah[mi][3], base + off);
                ldsm4(al[mi][0], al[mi][1], al[mi][2], al[mi][3], base + ATILE + off);
            }
            const int kbB = (kk * 16 + b_k8) * 2;
#pragma unroll
            for (int nip = 0; nip < 4; nip++) {
                uint32_t bh[2][2];
                uint32_t off = SWZ((wn * 64 + nip * 16 + b_row) * 128 + kbB);
                ldsm4(bh[0][0], bh[0][1], bh[1][0], bh[1][1], base + 2 * ATILE + off);
#pragma unroll
                for (int mi = 0; mi < 4; mi++)
#pragma unroll
                    for (int nj = 0; nj < 2; nj++) {
                        float* a = acc[mi][nip * 2 + nj];
                        mma16816(a, ah[mi][0], ah[mi][1], ah[mi][2], ah[mi][3],
                                 bh[nj][0], bh[nj][1]);
                        mma16816(a, al[mi][0], al[mi][1], al[mi][2], al[mi][3],
                                 bh[nj][0], bh[nj][1]);
                    }
            }
        }

        if (c + 2 < NCH) {
            __syncthreads();
            load_chunk(c & 1, c + 2);
        }
    }

    // ---- gemm1 epilogue: bias + relu + fp16 split -> Y tile in SMEM ----
    __syncthreads();
    {
        const int g = lane >> 2, t = lane & 3;
#pragma unroll
        for (int mi = 0; mi < 4; mi++) {
#pragma unroll
            for (int ni = 0; ni < 8; ni++) {
                int col = wn * 64 + ni * 8 + t * 2;        // 0..255
                float bv0 = g_b0f[col];
                float bv1 = g_b0f[col + 1];
                int kc  = col >> 6;
                int cb2 = (col & 63) * 2;
                int r0 = wm * 64 + mi * 16 + g;
                float v0 = fmaxf(acc[mi][ni][0] + bv0, 0.f);
                float v1 = fmaxf(acc[mi][ni][1] + bv1, 0.f);
                uint32_t ph, plo;
                split_pack(v0, v1, ph, plo);
                uint32_t o0 = kc * 16384 + SWZ(r0 * 128 + cb2);
                *(uint32_t*)(dsm + YBASE + o0) = ph;
                *(uint32_t*)(dsm + YBASE + YLOFF + o0) = plo;
                float v2 = fmaxf(acc[mi][ni][2] + bv0, 0.f);
                float v3 = fmaxf(acc[mi][ni][3] + bv1, 0.f);
                split_pack(v2, v3, ph, plo);
                uint32_t o1 = kc * 16384 + SWZ((r0 + 8) * 128 + cb2);
                *(uint32_t*)(dsm + YBASE + o1) = ph;
                *(uint32_t*)(dsm + YBASE + YLOFF + o1) = plo;
            }
        }
    }
    __syncthreads();

    // ---- phase 2 (gemm2): 128x128, warp tile 64x32, K=256 from SMEM ----
    float acc2[4][4][4];
#pragma unroll
    for (int mi = 0; mi < 4; mi++)
#pragma unroll
        for (int ni = 0; ni < 4; ni++)
#pragma unroll
            for (int e = 0; e < 4; e++) acc2[mi][ni][e] = 0.0f;

    for (int c = 0; c < 4; c++) {
        const uint32_t ybase = s0 + YBASE + c * 16384;
        const uint32_t wbase = s0 + WBASE + c * 16384;
#pragma unroll
        for (int kk = 0; kk < 4; kk++) {
            const int kb = (kk * 16 + a_k8) * 2;
            uint32_t ah[4][4], al[4][4];
#pragma unroll
            for (int mi = 0; mi < 4; mi++) {
                uint32_t off = SWZ((wm * 64 + mi * 16 + a_row) * 128 + kb);
                ldsm4(ah[mi][0], ah[mi][1], ah[mi][2], ah[mi][3], ybase + off);
                ldsm4(al[mi][0], al[mi][1], al[mi][2], al[mi][3], ybase + YLOFF + off);
            }
            uint32_t bh[4][2];
            const int kbB = (kk * 16 + b_k8) * 2;
#pragma unroll
            for (int nip = 0; nip < 2; nip++) {
                uint32_t off = SWZ((wn * 32 + nip * 16 + b_row) * 128 + kbB);
                ldsm4(bh[2 * nip][0], bh[2 * nip][1], bh[2 * nip + 1][0], bh[2 * nip + 1][1],
                      wbase + off);
            }
#pragma unroll
            for (int mi = 0; mi < 4; mi++)
#pragma unroll
                for (int ni = 0; ni < 4; ni++) {
                    mma16816(acc2[mi][ni], ah[mi][0], ah[mi][1], ah[mi][2], ah[mi][3],
                             bh[ni][0], bh[ni][1]);
                    mma16816(acc2[mi][ni], al[mi][0], al[mi][1], al[mi][2], al[mi][3],
                             bh[ni][0], bh[ni][1]);
                }
        }
    }

    // ---- final epilogue: bias + relu -> out (B, M1, NQ) ----
    {
        const int g = lane >> 2, t = lane & 3;
        int bb = p0 >> 13;
#pragma unroll
        for (int mi = 0; mi < 4; mi++) {
#pragma unroll
            for (int ni = 0; ni < 4; ni++) {
                int col = wn * 32 + ni * 8 + t * 2;
                float bv0 = g_b1f[col], bv1 = g_b1f[col + 1];
                int p = p0 + wm * 64 + mi * 16 + g;
                int n = p & (NQ - 1);
                size_t r0 = ((size_t)(bb * M1Q + col)) * NQ;
                size_t r1 = ((size_t)(bb * M1Q + col + 1)) * NQ;
                outF[r0 + n]     = fmaxf(acc2[mi][ni][0] + bv0, 0.f);
                outF[r1 + n]     = fmaxf(acc2[mi][ni][1] + bv1, 0.f);
                outF[r0 + n + 8] = fmaxf(acc2[mi][ni][2] + bv0, 0.f);
                outF[r1 + n + 8] = fmaxf(acc2[mi][ni][3] + bv1, 0.f);
            }
        }
    }
}

// ---------------- launch -----------------------------------------------------
extern "C" void kernel_launch(void* const* d_in, const int* in_sizes, int n_in,
                              void* d_out, int out_size) {
    const float* coords_1   = (const float*)d_in[0];
    const float* coords_2   = (const float*)d_in[1];
    const float* features_1 = (const float*)d_in[2];
    const float* features_2 = (const float*)d_in[3];
    const float* w0  = (const float*)d_in[4];
    const float* b0  = (const float*)d_in[5];
    const float* g0  = (const float*)d_in[6];
    const float* be0 = (const float*)d_in[7];
    const float* m0  = (const float*)d_in[8];
    const float* v0  = (const float*)d_in[9];
    const float* w1  = (const float*)d_in[10];
    const float* b1  = (const float*)d_in[11];
    const float* g1  = (const float*)d_in[12];
    const float* be1 = (const float*)d_in[13];
    const float* m1  = (const float*)d_in[14];
    const float* v1  = (const float*)d_in[15];
    float* out = (float*)d_out;

    const int SMEM = 196608;   // 128 KB gemm1 buffers (reused as Y) + 64 KB W1
    cudaFuncSetAttribute(gemm_fused_kernel,
                         cudaFuncAttributeMaxDynamicSharedMemorySize, SMEM);

    // 1: transpose + folds
    transpose_fold_kernel<<<dim3(65, 8, 16), dim3(32, 8)>>>(
        features_2, w0, b0, g0, be0, m0, v0, w1, b1, g1, be1, m1, v1);
    // 2: knn (two-phase fast scan + exact reselect)
    knn_kernel<<<dim3(NQ / 256, BQ), 256>>>(coords_1, coords_2);
    // 3: buildX (gather + f1 copy)
    buildx_kernel<<<PQ / 32, 256>>>(features_1);
    // 4: fused gemm1+gemm2  <-- profiled slot
    gemm_fused_kernel<<<PQ / 128, 256, SMEM>>>(out);
}

// round 17
// speedup vs baseline: 1.0514x; 1.0514x over previous
#include <cuda_runtime.h>
#include <cuda_fp16.h>
#include <math.h>
#include <stdint.h>

// Problem constants
#define BQ   16
#define NQ   8192
#define SQ   2048
#define C1Q  128
#define C2Q  256
#define PQ   (BQ * NQ)      // 131072 points
#define KX   384            // C1 + C2 (GEMM1 K)
#define M0Q  256            // layer0 out channels
#define M1Q  128            // layer1 out channels
#define BN_EPS 1e-5f

// ---------------- scratch (static device globals; no cudaMalloc) ------------
__device__ float g_b0f[M0Q];
__device__ float g_b1f[M1Q];
__device__ __half g_w0h[M0Q * KX];                      // fp16 folded W0
__device__ __half g_w1h[M1Q * M0Q];                     // fp16 folded W1
__device__ float g_f2t[BQ * SQ * C2Q];                  // features_2 transposed [b][s][c]
__device__ __half g_xh[(size_t)PQ * KX];                // X hi fp16, K-major [p][k]
__device__ __half g_xl[(size_t)PQ * KX];                // X lo fp16
__device__ int   g_idx[PQ * 3];
__device__ float g_wt[PQ * 3];

// ---------------- PTX helpers (sm_80-level only; NO tcgen05) ----------------
__device__ __forceinline__ uint32_t smem_u32(const void* p) {
    uint32_t r;
    asm("{ .reg .u64 t; cvta.to.shared.u64 t, %1; cvt.u32.u64 %0, t; }" : "=r"(r) : "l"(p));
    return r;
}
__device__ __forceinline__ void cp16(uint32_t dst, const void* src) {
    asm volatile("cp.async.cg.shared.global [%0], [%1], 16;" :: "r"(dst), "l"(src));
}
#define CP_COMMIT() asm volatile("cp.async.commit_group;" ::: "memory")
#define CP_WAIT0()  asm volatile("cp.async.wait_group 0;" ::: "memory")
#define CP_WAIT1()  asm volatile("cp.async.wait_group 1;" ::: "memory")

#define SWZ(o) ((uint32_t)(o) ^ ((((uint32_t)(o)) >> 3) & 0x70u))

__device__ __forceinline__ void ldsm4(uint32_t& r0, uint32_t& r1, uint32_t& r2,
                                      uint32_t& r3, uint32_t addr) {
    asm volatile("ldmatrix.sync.aligned.m8n8.x4.shared.b16 {%0,%1,%2,%3}, [%4];"
                 : "=r"(r0), "=r"(r1), "=r"(r2), "=r"(r3) : "r"(addr));
}
// fp16 MMA with fp32 accumulate
__device__ __forceinline__ void mma16816(float* d, uint32_t a0, uint32_t a1,
                                         uint32_t a2, uint32_t a3,
                                         uint32_t b0, uint32_t b1) {
    asm volatile(
        "mma.sync.aligned.m16n8k16.row.col.f32.f16.f16.f32 "
        "{%0,%1,%2,%3}, {%4,%5,%6,%7}, {%8,%9}, {%0,%1,%2,%3};"
        : "+f"(d[0]), "+f"(d[1]), "+f"(d[2]), "+f"(d[3])
        : "r"(a0), "r"(a1), "r"(a2), "r"(a3), "r"(b0), "r"(b1));
}

// fp16 hi/lo split of two floats, packed into two uint32 (lo16=v0, hi16=v1)
__device__ __forceinline__ void split_pack(float v0, float v1, uint32_t& ph, uint32_t& plo) {
    __half h0 = __float2half_rn(v0), h1 = __float2half_rn(v1);
    float r0 = v0 - __half2float(h0), r1 = v1 - __half2float(h1);
    __half l0 = __float2half_rn(r0), l1 = __float2half_rn(r1);
    ph  = (uint32_t)__half_as_ushort(h0) | ((uint32_t)__half_as_ushort(h1) << 16);
    plo = (uint32_t)__half_as_ushort(l0) | ((uint32_t)__half_as_ushort(l1) << 16);
}

// ---------------- transpose features_2 + BN folds (merged) -------------------
__global__ void transpose_fold_kernel(const float* __restrict__ f2,
                                      const float* __restrict__ w0, const float* __restrict__ b0,
                                      const float* __restrict__ g0, const float* __restrict__ be0,
                                      const float* __restrict__ m0, const float* __restrict__ v0,
                                      const float* __restrict__ w1, const float* __restrict__ b1,
                                      const float* __restrict__ g1, const float* __restrict__ be1,
                                      const float* __restrict__ m1, const float* __restrict__ v1) {
    if (blockIdx.x == 64) {
        int tid  = threadIdx.y * 32 + threadIdx.x;                      // 0..255
        int base = (blockIdx.y * 16 + blockIdx.z) * 256 + tid;          // 0..32767
        for (int e = base; e < M0Q * KX; e += 32768) {
            int o = e / KX;
            float s = g0[o] * rsqrtf(v0[o] + BN_EPS);
            g_w0h[e] = __float2half_rn(w0[e] * s);
        }
        {
            int e = base;
            int o = e >> 8;
            float s = g1[o] * rsqrtf(v1[o] + BN_EPS);
            g_w1h[e] = __float2half_rn(w1[e] * s);
        }
        if (base < M0Q) {
            float s = g0[base] * rsqrtf(v0[base] + BN_EPS);
            g_b0f[base] = (b0[base] - m0[base]) * s + be0[base];
        }
        if (base < M1Q) {
            float s = g1[base] * rsqrtf(v1[base] + BN_EPS);
            g_b1f[base] = (b1[base] - m1[base]) * s + be1[base];
        }
        return;
    }
    __shared__ float tile[32][33];
    int b  = blockIdx.z;
    int s0 = blockIdx.x * 32;
    int c0 = blockIdx.y * 32;
    int tx = threadIdx.x, ty = threadIdx.y;
    int s = s0 + tx;
#pragma unroll
    for (int r = 0; r < 4; r++) {
        int c = c0 + ty + r * 8;
        tile[ty + r * 8][tx] = f2[((size_t)b * C2Q + c) * SQ + s];
    }
    __syncthreads();
    int c = c0 + tx;
#pragma unroll
    for (int r = 0; r < 4; r++) {
        int s2 = s0 + ty + r * 8;
        g_f2t[((size_t)b * SQ + s2) * C2Q + c] = tile[tx][ty + r * 8];
    }
}

// ---------------- 3-NN + inverse-distance weights (reference rounding) -------
// Proven scalar _rn sequence: error stays correlated with the reference so
// near-tie neighbor selections agree. DO NOT alter this arithmetic (R15/R16
// attempts both failed).
__global__ __launch_bounds__(256) void knn_kernel(const float* __restrict__ c1,
                                                  const float* __restrict__ c2) {
    __shared__ float4 sc[SQ];
    int b = blockIdx.y;
    const float* cb = c2 + (size_t)b * 3 * SQ;
    for (int i = threadIdx.x; i < SQ; i += 256) {
        float x = cb[i], y = cb[SQ + i], z = cb[2 * SQ + i];
        float sq = __fadd_rn(__fadd_rn(__fmul_rn(x, x), __fmul_rn(y, y)), __fmul_rn(z, z));
        sc[i] = make_float4(x, y, z, sq);
    }
    __syncthreads();

    int n = blockIdx.x * 256 + threadIdx.x;
    const float* qb = c1 + (size_t)b * 3 * NQ;
    float x1 = qb[n], y1 = qb[NQ + n], z1 = qb[2 * NQ + n];
    float q2 = __fadd_rn(__fadd_rn(__fmul_rn(x1, x1), __fmul_rn(y1, y1)), __fmul_rn(z1, z1));

    float d0 = 1e30f, d1 = 1e30f, d2 = 1e30f;
    int   i0 = 0, i1 = 0, i2 = 0;
#pragma unroll 4
    for (int s = 0; s < SQ; s++) {
        float4 c = sc[s];
        float dot = __fadd_rn(__fadd_rn(__fmul_rn(x1, c.x), __fmul_rn(y1, c.y)),
                              __fmul_rn(z1, c.z));
        float d = __fsub_rn(__fadd_rn(q2, c.w), __fadd_rn(dot, dot));
        if (d < d2) {
            if (d < d1) {
                d2 = d1; i2 = i1;
                if (d < d0) { d1 = d0; i1 = i0; d0 = d; i0 = s; }
                else        { d1 = d;  i1 = s; }
            } else { d2 = d; i2 = s; }
        }
    }
    d0 = fmaxf(d0, 1e-10f); d1 = fmaxf(d1, 1e-10f); d2 = fmaxf(d2, 1e-10f);
    float r0 = __fdiv_rn(1.0f, d0), r1 = __fdiv_rn(1.0f, d1), r2 = __fdiv_rn(1.0f, d2);
    float rs = __fadd_rn(__fadd_rn(r0, r1), r2);
    int p = b * NQ + n;
    g_idx[p * 3 + 0] = i0; g_idx[p * 3 + 1] = i1; g_idx[p * 3 + 2] = i2;
    g_wt[p * 3 + 0] = __fdiv_rn(r0, rs);
    g_wt[p * 3 + 1] = __fdiv_rn(r1, rs);
    g_wt[p * 3 + 2] = __fdiv_rn(r2, rs);
}

// ---------------- buildX: gather/interpolate + f1 copy -> X fp16 hi/lo -------
__global__ __launch_bounds__(256) void buildx_kernel(const float* __restrict__ f1) {
    __shared__ float tile[32][257];
    __shared__ int   sidx[32][3];
    __shared__ float swt[32][3];
    int p0 = blockIdx.x * 32;
    int b  = p0 >> 13;
    int n0 = p0 & (NQ - 1);
    int t = threadIdx.x;
    if (t < 96) {
        int pl = t / 3, k = t - pl * 3;
        sidx[pl][k] = g_idx[(p0 + pl) * 3 + k];
        swt[pl][k]  = g_wt[(p0 + pl) * 3 + k];
    }
    __syncthreads();

    uint32_t* xh = (uint32_t*)g_xh;
    uint32_t* xl = (uint32_t*)g_xl;
    int warp = t >> 5, lane = t & 31;

    // ---- phase A: gather + interpolate ----
    const float* fbase = g_f2t + (size_t)b * SQ * C2Q;
#pragma unroll
    for (int it = 0; it < 4; it++) {
        int pl = warp * 4 + it;
        const float* fa = fbase + (size_t)sidx[pl][0] * C2Q;
        const float* fb = fbase + (size_t)sidx[pl][1] * C2Q;
        const float* fc = fbase + (size_t)sidx[pl][2] * C2Q;
        float w0 = swt[pl][0], w1 = swt[pl][1], w2 = swt[pl][2];
#pragma unroll
        for (int q = 0; q < 2; q++) {
            int c = lane * 4 + q * 128;
            float4 a = *(const float4*)(fa + c);
            float4 bb = *(const float4*)(fb + c);
            float4 cv = *(const float4*)(fc + c);
            tile[pl][c + 0] = __fadd_rn(__fadd_rn(__fmul_rn(a.x, w0), __fmul_rn(bb.x, w1)), __fmul_rn(cv.x, w2));
            tile[pl][c + 1] = __fadd_rn(__fadd_rn(__fmul_rn(a.y, w0), __fmul_rn(bb.y, w1)), __fmul_rn(cv.y, w2));
            tile[pl][c + 2] = __fadd_rn(__fadd_rn(__fmul_rn(a.z, w0), __fmul_rn(bb.z, w1)), __fmul_rn(cv.z, w2));
            tile[pl][c + 3] = __fadd_rn(__fadd_rn(__fmul_rn(a.w, w0), __fmul_rn(bb.w, w1)), __fmul_rn(cv.w, w2));
        }
    }
    __syncthreads();
#pragma unroll
    for (int it = 0; it < 16; it++) {
        int i = t + it * 256;
        int pl = i >> 7, c2 = i & 127;
        uint32_t ph, plo;
        split_pack(tile[pl][c2 * 2], tile[pl][c2 * 2 + 1], ph, plo);
        size_t p = (size_t)(p0 + pl);
        xh[p * (KX / 2) + 64 + c2] = ph;
        xl[p * (KX / 2) + 64 + c2] = plo;
    }
    __syncthreads();

    // ---- phase B: features_1 copy through tile ----
#pragma unroll
    for (int it = 0; it < 16; it++) {
        int i = t + it * 256;            // 0..4095
        int c = i >> 5, n = i & 31;
        tile[n][c] = f1[((size_t)b * C1Q + c) * NQ + n0 + n];
    }
    __syncthreads();
#pragma unroll
    for (int it = 0; it < 8; it++) {
        int i = t + it * 256;            // 0..2047
        int pl = i >> 6, c2 = i & 63;
        uint32_t ph, plo;
        split_pack(tile[pl][c2 * 2], tile[pl][c2 * 2 + 1], ph, plo);
        size_t p = (size_t)(p0 + pl);
        xh[p * (KX / 2) + c2] = ph;
        xl[p * (KX / 2) + c2] = plo;
    }
}

// ---------------- fused GEMM1+GEMM2 (fp16x2 mma.sync) ------------------------
// Phase 1 (gemm1): CTA 128x256, warp tile 64x64, K=384 from gmem (double buf).
// Y (bias+relu, fp16 hi/lo split) is written to SMEM instead of gmem.
// Phase 2 (gemm2): same CTA contracts K=256 over the SMEM-resident Y with
// W1 (prefetched at kernel start), writes final output.
__global__ __launch_bounds__(256, 1) void gemm_fused_kernel(float* __restrict__ outF) {
    constexpr int NCH    = KX / 64;            // 6
    constexpr int ATILE  = 128 * 128;          // 16 KB per A half-chunk
    constexpr int BTILE  = M0Q * 128;          // 32 KB W0 chunk
    constexpr int CHUNK  = 2 * ATILE + BTILE;  // 64 KB
    constexpr int YBASE  = 0;
    constexpr int YLOFF  = 4 * 16384;          // 64 KB
    constexpr int WBASE  = 2 * CHUNK;          // 131072

    extern __shared__ __align__(1024) char dsm[];
    const uint32_t s0 = smem_u32(dsm);

    const int tid  = threadIdx.x;
    const int warp = tid >> 5;
    const int lane = tid & 31;
    const int wm   = warp >> 2;                // 0..1
    const int wn   = warp & 3;                 // 0..3
    const int p0   = blockIdx.x * 128;

    const int a_row = (lane & 15);
    const int a_k8  = (lane >> 4) * 8;
    const int b_row = ((lane >> 4) & 1) * 8 + (lane & 7);
    const int b_k8  = ((lane >> 3) & 1) * 8;

    // ---- prefetch W1 (64 KB) as the first cp.async group ----
    {
#pragma unroll
        for (int it = 0; it < 16; it++) {
            int i = tid + it * 256;            // 0..4095
            int kc  = i >> 10;                 // 0..3
            int r   = (i >> 3) & 127;
            int c16 = (i & 7) * 16;
            uint32_t dst = s0 + WBASE + kc * 16384 + SWZ(r * 128 + c16);
            const char* src = (const char*)g_w1h + (size_t)r * (M0Q * 2) + kc * 128 + c16;
            cp16(dst, src);
        }
        CP_COMMIT();
    }

    float acc[4][8][4];
#pragma unroll
    for (int mi = 0; mi < 4; mi++)
#pragma unroll
        for (int ni = 0; ni < 8; ni++)
#pragma unroll
            for (int e = 0; e < 4; e++) acc[mi][ni][e] = 0.0f;

    auto load_chunk = [&](int buf, int ch) {
        const uint32_t base = s0 + buf * CHUNK;
        const size_t rs = (size_t)KX * 2;
        const char* gAh = (const char*)g_xh + (size_t)p0 * rs + (size_t)ch * 128;
        const char* gAl = (const char*)g_xl + (size_t)p0 * rs + (size_t)ch * 128;
        const char* gWh = (const char*)g_w0h + (size_t)ch * 128;
#pragma unroll
        for (int it = 0; it < 4; it++) {
            int i = tid + it * 256;            // 0..1023 (A rows)
            int row = i >> 3, c16 = (i & 7) * 16;
            uint32_t sw = SWZ(row * 128 + c16);
            size_t go = (size_t)row * rs + c16;
            cp16(base + sw,         gAh + go);
            cp16(base + ATILE + sw, gAl + go);
        }
#pragma unroll
        for (int it = 0; it < 8; it++) {
            int i = tid + it * 256;            // 0..2047 (W rows)
            int row = i >> 3, c16 = (i & 7) * 16;
            uint32_t sw = SWZ(row * 128 + c16);
            size_t go = (size_t)row * rs + c16;
            cp16(base + 2 * ATILE + sw, gWh + go);
        }
        CP_COMMIT();
    };

    load_chunk(0, 0);
    load_chunk(1, 1);

    for (int c = 0; c < NCH; c++) {
        if (c + 1 < NCH) { CP_WAIT1(); } else { CP_WAIT0(); }
        __syncthreads();

        const uint32_t base = s0 + (c & 1) * CHUNK;
#pragma unroll
        for (int kk = 0; kk < 4; kk++) {
            const int kb = (kk * 16 + a_k8) * 2;
            uint32_t ah[4][4], al[4][4];
#pragma unroll
            for (int mi = 0; mi < 4; mi++) {
                uint32_t off = SWZ((wm * 64 + mi * 16 + a_row) * 128 + kb);
                ldsm4(ah[mi][0], ah[mi][1], ah[mi][2], ah[mi][3], base + off);
                ldsm4(al[mi][0], al[mi][1], al[mi][2], al[mi][3], base + ATILE + off);
            }
            const int kbB = (kk * 16 + b_k8) * 2;
#pragma unroll
            for (int nip = 0; nip < 4; nip++) {
                uint32_t bh[2][2];
                uint32_t off = SWZ((wn * 64 + nip * 16 + b_row) * 128 + kbB);
                ldsm4(bh[0][0], bh[0][1], bh[1][0], bh[1][1], base + 2 * ATILE + off);
#pragma unroll
                for (int mi = 0; mi < 4; mi++)
#pragma unroll
                    for (int nj = 0; nj < 2; nj++) {
                        float* a = acc[mi][nip * 2 + nj];
                        mma16816(a, ah[mi][0], ah[mi][1], ah[mi][2], ah[mi][3],
                                 bh[nj][0], bh[nj][1]);
                        mma16816(a, al[mi][0], al[mi][1], al[mi][2], al[mi][3],
                                 bh[nj][0], bh[nj][1]);
                    }
            }
        }

        if (c + 2 < NCH) {
            __syncthreads();
            load_chunk(c & 1, c + 2);
        }
    }

    // ---- gemm1 epilogue: bias + relu + fp16 split -> Y tile in SMEM ----
    __syncthreads();
    {
        const int g = lane >> 2, t = lane & 3;
#pragma unroll
        for (int mi = 0; mi < 4; mi++) {
#pragma unroll
            for (int ni = 0; ni < 8; ni++) {
                int col = wn * 64 + ni * 8 + t * 2;        // 0..255
                float bv0 = g_b0f[col];
                float bv1 = g_b0f[col + 1];
                int kc  = col >> 6;
                int cb2 = (col & 63) * 2;
                int r0 = wm * 64 + mi * 16 + g;
                float v0 = fmaxf(acc[mi][ni][0] + bv0, 0.f);
                float v1 = fmaxf(acc[mi][ni][1] + bv1, 0.f);
                uint32_t ph, plo;
                split_pack(v0, v1, ph, plo);
                uint32_t o0 = kc * 16384 + SWZ(r0 * 128 + cb2);
                *(uint32_t*)(dsm + YBASE + o0) = ph;
                *(uint32_t*)(dsm + YBASE + YLOFF + o0) = plo;
                float v2 = fmaxf(acc[mi][ni][2] + bv0, 0.f);
                float v3 = fmaxf(acc[mi][ni][3] + bv1, 0.f);
                split_pack(v2, v3, ph, plo);
                uint32_t o1 = kc * 16384 + SWZ((r0 + 8) * 128 + cb2);
                *(uint32_t*)(dsm + YBASE + o1) = ph;
                *(uint32_t*)(dsm + YBASE + YLOFF + o1) = plo;
            }
        }
    }
    __syncthreads();

    // ---- phase 2 (gemm2): 128x128, warp tile 64x32, K=256 from SMEM ----
    float acc2[4][4][4];
#pragma unroll
    for (int mi = 0; mi < 4; mi++)
#pragma unroll
        for (int ni = 0; ni < 4; ni++)
#pragma unroll
            for (int e = 0; e < 4; e++) acc2[mi][ni][e] = 0.0f;

    for (int c = 0; c < 4; c++) {
        const uint32_t ybase = s0 + YBASE + c * 16384;
        const uint32_t wbase = s0 + WBASE + c * 16384;
#pragma unroll
        for (int kk = 0; kk < 4; kk++) {
            const int kb = (kk * 16 + a_k8) * 2;
            uint32_t ah[4][4], al[4][4];
#pragma unroll
            for (int mi = 0; mi < 4; mi++) {
                uint32_t off = SWZ((wm * 64 + mi * 16 + a_row) * 128 + kb);
                ldsm4(ah[mi][0], ah[mi][1], ah[mi][2], ah[mi][3], ybase + off);
                ldsm4(al[mi][0], al[mi][1], al[mi][2], al[mi][3], ybase + YLOFF + off);
            }
            uint32_t bh[4][2];
            const int kbB = (kk * 16 + b_k8) * 2;
#pragma unroll
            for (int nip = 0; nip < 2; nip++) {
                uint32_t off = SWZ((wn * 32 + nip * 16 + b_row) * 128 + kbB);
                ldsm4(bh[2 * nip][0], bh[2 * nip][1], bh[2 * nip + 1][0], bh[2 * nip + 1][1],
                      wbase + off);
            }
#pragma unroll
            for (int mi = 0; mi < 4; mi++)
#pragma unroll
                for (int ni = 0; ni < 4; ni++) {
                    mma16816(acc2[mi][ni], ah[mi][0], ah[mi][1], ah[mi][2], ah[mi][3],
                             bh[ni][0], bh[ni][1]);
                    mma16816(acc2[mi][ni], al[mi][0], al[mi][1], al[mi][2], al[mi][3],
                             bh[ni][0], bh[ni][1]);
                }
        }
    }

    // ---- final epilogue: bias + relu -> out (B, M1, NQ) ----
    {
        const int g = lane >> 2, t = lane & 3;
        int bb = p0 >> 13;
#pragma unroll
        for (int mi = 0; mi < 4; mi++) {
#pragma unroll
            for (int ni = 0; ni < 4; ni++) {
                int col = wn * 32 + ni * 8 + t * 2;
                float bv0 = g_b1f[col], bv1 = g_b1f[col + 1];
                int p = p0 + wm * 64 + mi * 16 + g;
                int n = p & (NQ - 1);
                size_t r0 = ((size_t)(bb * M1Q + col)) * NQ;
                size_t r1 = ((size_t)(bb * M1Q + col + 1)) * NQ;
                outF[r0 + n]     = fmaxf(acc2[mi][ni][0] + bv0, 0.f);
                outF[r1 + n]     = fmaxf(acc2[mi][ni][1] + bv1, 0.f);
                outF[r0 + n + 8] = fmaxf(acc2[mi][ni][2] + bv0, 0.f);
                outF[r1 + n + 8] = fmaxf(acc2[mi][ni][3] + bv1, 0.f);
            }
        }
    }
}

// ---------------- launch -----------------------------------------------------
extern "C" void kernel_launch(void* const* d_in, const int* in_sizes, int n_in,
                              void* d_out, int out_size) {
    const float* coords_1   = (const float*)d_in[0];
    const float* coords_2   = (const float*)d_in[1];
    const float* features_1 = (const float*)d_in[2];
    const float* features_2 = (const float*)d_in[3];
    const float* w0  = (const float*)d_in[4];
    const float* b0  = (const float*)d_in[5];
    const float* g0  = (const float*)d_in[6];
    const float* be0 = (const float*)d_in[7];
    const float* m0  = (const float*)d_in[8];
    const float* v0  = (const float*)d_in[9];
    const float* w1  = (const float*)d_in[10];
    const float* b1  = (const float*)d_in[11];
    const float* g1  = (const float*)d_in[12];
    const float* be1 = (const float*)d_in[13];
    const float* m1  = (const float*)d_in[14];
    const float* v1  = (const float*)d_in[15];
    float* out = (float*)d_out;

    const int SMEM = 196608;   // 128 KB gemm1 buffers (reused as Y) + 64 KB W1
    cudaFuncSetAttribute(gemm_fused_kernel,
                         cudaFuncAttributeMaxDynamicSharedMemorySize, SMEM);

    // 1: transpose + folds
    transpose_fold_kernel<<<dim3(65, 8, 16), dim3(32, 8)>>>(
        features_2, w0, b0, g0, be0, m0, v0, w1, b1, g1, be1, m1, v1);
    // 2: knn (proven scalar reference-rounded distances)
    knn_kernel<<<dim3(NQ / 256, BQ), 256>>>(coords_1, coords_2);
    // 3: buildX (gather + f1 copy)
    buildx_kernel<<<PQ / 32, 256>>>(features_1);
    // 4: fused gemm1+gemm2
    gemm_fused_kernel<<<PQ / 128, 256, SMEM>>>(out);
}